// round 14
// baseline (speedup 1.0000x reference)
#include <cuda_runtime.h>
#include <stdint.h>
#include <math.h>

#define BATCH 8192
#define ROWS  65536

// Scratch (static device globals; allocation-free per harness rules)
__device__ float g_AB[(size_t)ROWS * 512];  // per row: [A_rel(128)|B_rel(128)|A_att(128)|B_att(128)]
__device__ float g_SDs[(size_t)BATCH * 64]; // per-batch summed self_dyn
__device__ float g_Wt[2 * 8192];            // tf32-rounded W_rel1 / W_att1, [n=64][k=128]
// Prepacked k1 weights, bf16 hi/lo, swizzled smem-image layout.
__device__ __align__(16) uint16_t g_WpkH[45056];
__device__ __align__(16) uint16_t g_WpkL[45056];

__device__ __forceinline__ float eluf(float x) {
    return x > 0.f ? x : (__expf(x) - 1.f);
}
__device__ __forceinline__ uint32_t smem_u32(const void* p) {
    uint32_t a;
    asm("{ .reg .u64 t; cvta.to.shared.u64 t, %1; cvt.u32.u64 %0, t; }" : "=r"(a) : "l"(p));
    return a;
}
__device__ __forceinline__ void split2(float x0, float x1, uint32_t& hi, uint32_t& lo) {
    uint32_t h;
    asm("cvt.rn.bf16x2.f32 %0, %1, %2;" : "=r"(h) : "f"(x1), "f"(x0));
    float h0 = __uint_as_float(h << 16);
    float h1 = __uint_as_float(h & 0xffff0000u);
    float l0 = x0 - h0, l1 = x1 - h1;
    uint32_t l;
    asm("cvt.rn.bf16x2.f32 %0, %1, %2;" : "=r"(l) : "f"(l1), "f"(l0));
    hi = h; lo = l;
}
__device__ __forceinline__ uint32_t f2tf32(float x) {
    uint32_t r;
    asm("cvt.rna.tf32.f32 %0, %1;" : "=r"(r) : "f"(x));
    return r;
}
__device__ __forceinline__ void ldsm4(uint32_t r[4], uint32_t addr) {
    asm volatile("ldmatrix.sync.aligned.m8n8.x4.shared.b16 {%0,%1,%2,%3}, [%4];"
        : "=r"(r[0]), "=r"(r[1]), "=r"(r[2]), "=r"(r[3]) : "r"(addr));
}
__device__ __forceinline__ void mma16816(float d[4], const uint32_t a[4],
                                         uint32_t b0, uint32_t b1) {
    asm volatile("mma.sync.aligned.m16n8k16.row.col.f32.bf16.bf16.f32 "
        "{%0,%1,%2,%3}, {%4,%5,%6,%7}, {%8,%9}, {%0,%1,%2,%3};"
        : "+f"(d[0]), "+f"(d[1]), "+f"(d[2]), "+f"(d[3])
        : "r"(a[0]), "r"(a[1]), "r"(a[2]), "r"(a[3]), "r"(b0), "r"(b1));
}
__device__ __forceinline__ void mma_tf32(float d[4], const uint32_t a[4],
                                         uint32_t b0, uint32_t b1) {
    asm volatile("mma.sync.aligned.m16n8k8.row.col.f32.tf32.tf32.f32 "
        "{%0,%1,%2,%3}, {%4,%5,%6,%7}, {%8,%9}, {%0,%1,%2,%3};"
        : "+f"(d[0]), "+f"(d[1]), "+f"(d[2]), "+f"(d[3])
        : "r"(a[0]), "r"(a[1]), "r"(a[2]), "r"(a[3]), "r"(b0), "r"(b1));
}

// ---------------------------------------------------------------------------
// K0: prepack k1 weights (bf16 hi/lo) + tf32-rounded W_rel1/W_att1 transposes.
// ---------------------------------------------------------------------------
__device__ __forceinline__ float catw(const float* Wr, const float* Wa, int k, int g) {
    if (g < 128) return Wr[k*128 + g];
    if (g < 256) return Wr[(64+k)*128 + (g-128)];
    if (g < 384) return Wa[k*128 + (g-256)];
    return Wa[(64+k)*128 + (g-384)];
}

__global__ void k0_kernel(const float* __restrict__ W_enc,
                          const float* __restrict__ W_self0,
                          const float* __restrict__ W_self1,
                          const float* __restrict__ W_rel0,
                          const float* __restrict__ W_att0,
                          const float* __restrict__ W_rel1,
                          const float* __restrict__ W_att1)
{
    int e = blockIdx.x * 256 + threadIdx.x;
    if (e < 22528) {
        int tile = e >> 11;
        int idx = e & 2047;
        int n = idx & 63, k0 = (idx >> 6) * 2;
        float v0, v1;
        if (tile == 0)      { v0 = W_enc[k0*64+n];   v1 = W_enc[(k0+1)*64+n]; }
        else if (tile == 1) { v0 = W_self0[k0*64+n]; v1 = W_self0[(k0+1)*64+n]; }
        else if (tile == 2) { v0 = W_self1[k0*64+n]; v1 = W_self1[(k0+1)*64+n]; }
        else {
            int g = (tile - 3) * 64 + n;
            v0 = catw(W_rel0, W_att0, k0, g);
            v1 = catw(W_rel0, W_att0, k0 + 1, g);
        }
        uint32_t hb, lb;
        split2(v0, v1, hb, lb);
        uint32_t off16 = (uint32_t)(tile*4096 + n*64 + (((k0>>3)*8) ^ ((n&7)*8)) + (k0&7));
        *(uint32_t*)((char*)g_WpkH + off16*2) = hb;
        *(uint32_t*)((char*)g_WpkL + off16*2) = lb;
    } else if (e < 38912) {
        int i2 = e - 22528;
        int hf = i2 >> 13;
        int i = i2 & 8191;
        int n = i >> 7, k = i & 127;
        float w = hf ? W_att1[k*64 + n] : W_rel1[k*64 + n];
        g_Wt[hf*8192 + n*128 + k] = __uint_as_float(f2tf32(w));
    }
}

// ---------------------------------------------------------------------------
// K1v2b: unchanged from R12 (passed; g_SDs pre-reduction).
// ---------------------------------------------------------------------------
#define K1_XHI 0
#define K1_XLO 16384
#define K1_EHI 32768
#define K1_ELO 49152
#define K1_WSH 65536
#define K1_WSL 90112
#define K1_WC  114688
#define K1_S01 147456
#define SMEM1_BYTES 148480

__device__ __forceinline__ void gemm_k64(uint32_t AH, uint32_t AL,
                                         uint32_t BH, uint32_t BL,
                                         int wm, int wn, int lane, float d[2][2][4])
{
    const int nloc = wn*16 + (lane & 7) + ((lane >> 4) << 3);
    const int nsw  = (lane & 7) * 16;
    const int bkc0 = (lane >> 3) & 1;
    const int rloc0 = wm*32 + (lane & 15);
    const int rsw  = (lane & 7) * 16;
    const int akc0 = lane >> 4;
#pragma unroll
    for (int ks = 0; ks < 4; ks++) {
        uint32_t bh[4], bl[4];
        {
            uint32_t boff = (uint32_t)(nloc*128 + (((ks*2 + bkc0)*16) ^ nsw));
            ldsm4(bh, BH + boff);
            ldsm4(bl, BL + boff);
        }
#pragma unroll
        for (int mt = 0; mt < 2; mt++) {
            uint32_t aoff = (uint32_t)((rloc0 + mt*16)*128 + (((ks*2 + akc0)*16) ^ rsw));
            uint32_t ah[4], al[4];
            ldsm4(ah, AH + aoff);
            ldsm4(al, AL + aoff);
            mma16816(d[mt][0], ah, bh[0], bh[1]);
            mma16816(d[mt][1], ah, bh[2], bh[3]);
            mma16816(d[mt][0], al, bh[0], bh[1]);
            mma16816(d[mt][1], al, bh[2], bh[3]);
            mma16816(d[mt][0], ah, bl[0], bl[1]);
            mma16816(d[mt][1], ah, bl[2], bl[3]);
        }
    }
}
#define K1_ZERO(d) { _Pragma("unroll") for (int _m=0;_m<2;_m++) _Pragma("unroll") for (int _n=0;_n<2;_n++) _Pragma("unroll") for (int _q=0;_q<4;_q++) (d)[_m][_n][_q]=0.f; }

__global__ __launch_bounds__(512, 1)
void k1_kernel(const float* __restrict__ s,
               const float* __restrict__ b_enc,
               const float* __restrict__ b_self0,
               const float* __restrict__ b_self1)
{
    extern __shared__ char smc[];
    const uint32_t smb = smem_u32(smc);
    const int tid = threadIdx.x, lane = tid & 31, wid = tid >> 5;
    const int wm = wid & 3, wn = wid >> 2;
    const int row0 = blockIdx.x * 128;
    float* s01 = (float*)(smc + K1_S01);

    {
        const uint4* srcH = (const uint4*)g_WpkH;
        const uint4* srcL = (const uint4*)g_WpkL;
#pragma unroll
        for (int q = 0; q < 3; q++) {
            ((uint4*)(smc + K1_WSH))[tid + q*512] = srcH[tid + q*512];
            ((uint4*)(smc + K1_WSL))[tid + q*512] = srcL[tid + q*512];
        }
    }
    uint4 pH = ((const uint4*)g_WpkH)[1536 + tid];
    uint4 pL = ((const uint4*)g_WpkL)[1536 + tid];

#pragma unroll
    for (int it = 0; it < 4; it++) {
        int idx = tid + it*512;
        int r = idx >> 4, kq = idx & 15, k0 = kq*4;
        float4 v = *(const float4*)(s + (size_t)(row0 + r)*64 + k0);
        if (kq == 0) { s01[r*2] = v.x; s01[r*2+1] = v.y; }
        uint32_t h0, l0, h1, l1;
        split2(v.x, v.y, h0, l0);
        split2(v.z, v.w, h1, l1);
        uint32_t off = (uint32_t)(r*128 + (((k0>>3)*16) ^ ((r&7)*16)) + (k0&7)*2);
        *(uint2*)(smc + K1_XHI + off) = make_uint2(h0, h1);
        *(uint2*)(smc + K1_XLO + off) = make_uint2(l0, l1);
    }

    const int c0b = wn*16 + (lane & 3)*2;
    float be[4], bs0[4], bs1[4];
    be[0]  = b_enc[c0b];    be[1]  = b_enc[c0b+1];
    be[2]  = b_enc[c0b+8];  be[3]  = b_enc[c0b+9];
    bs0[0] = b_self0[c0b];   bs0[1] = b_self0[c0b+1];
    bs0[2] = b_self0[c0b+8]; bs0[3] = b_self0[c0b+9];
    bs1[0] = b_self1[c0b];   bs1[1] = b_self1[c0b+1];
    bs1[2] = b_self1[c0b+8]; bs1[3] = b_self1[c0b+9];
    __syncthreads();

    float d[2][2][4];

    K1_ZERO(d);
    gemm_k64(smb + K1_XHI, smb + K1_XLO, smb + K1_WSH, smb + K1_WSL, wm, wn, lane, d);
#pragma unroll
    for (int mt = 0; mt < 2; mt++)
#pragma unroll
    for (int nt = 0; nt < 2; nt++)
#pragma unroll
    for (int h = 0; h < 2; h++) {
        int r = wm*32 + mt*16 + (lane >> 2) + h*8;
        int c0 = wn*16 + nt*8 + (lane & 3)*2;
        float v0 = d[mt][nt][h*2]     + be[nt*2];
        float v1 = d[mt][nt][h*2 + 1] + be[nt*2 + 1];
        if (c0 == 0) { v0 = s01[r*2]; v1 = s01[r*2+1]; }
        uint32_t hb, lb;
        split2(v0, v1, hb, lb);
        uint32_t off = (uint32_t)(r*128 + (((c0>>3)*16) ^ ((r&7)*16)) + (c0&7)*2);
        *(uint32_t*)(smc + K1_EHI + off) = hb;
        *(uint32_t*)(smc + K1_ELO + off) = lb;
    }
    __syncthreads();

    K1_ZERO(d);
    gemm_k64(smb + K1_EHI, smb + K1_ELO, smb + K1_WSH + 8192, smb + K1_WSL + 8192,
             wm, wn, lane, d);
    float hf[2][2][4];
#pragma unroll
    for (int mt = 0; mt < 2; mt++)
#pragma unroll
    for (int nt = 0; nt < 2; nt++)
#pragma unroll
    for (int h = 0; h < 2; h++) {
        int r = wm*32 + mt*16 + (lane >> 2) + h*8;
        int c0 = wn*16 + nt*8 + (lane & 3)*2;
        float v0 = eluf(d[mt][nt][h*2]     + bs0[nt*2]);
        float v1 = eluf(d[mt][nt][h*2 + 1] + bs0[nt*2 + 1]);
        hf[mt][nt][h*2] = v0; hf[mt][nt][h*2+1] = v1;
        uint32_t hb, lb;
        split2(v0, v1, hb, lb);
        uint32_t off = (uint32_t)(r*128 + (((c0>>3)*16) ^ ((r&7)*16)) + (c0&7)*2);
        *(uint32_t*)(smc + K1_XHI + off) = hb;
        *(uint32_t*)(smc + K1_XLO + off) = lb;
    }
    __syncthreads();

    *(uint4*)(smc + K1_WC + tid*16) = pH;
    *(uint4*)(smc + K1_WC + 8192 + tid*16) = pL;

    K1_ZERO(d);
    gemm_k64(smb + K1_XHI, smb + K1_XLO, smb + K1_WSH + 16384, smb + K1_WSL + 16384,
             wm, wn, lane, d);
#pragma unroll
    for (int mt = 0; mt < 2; mt++)
#pragma unroll
    for (int nt = 0; nt < 2; nt++) {
        float s0 = d[mt][nt][0] + bs1[nt*2]     + hf[mt][nt][0];
        float s1 = d[mt][nt][1] + bs1[nt*2 + 1] + hf[mt][nt][1];
        float s2 = d[mt][nt][2] + bs1[nt*2]     + hf[mt][nt][2];
        float s3 = d[mt][nt][3] + bs1[nt*2 + 1] + hf[mt][nt][3];
#pragma unroll
        for (int m = 4; m <= 16; m <<= 1) {
            s0 += __shfl_xor_sync(0xffffffffu, s0, m);
            s1 += __shfl_xor_sync(0xffffffffu, s1, m);
            s2 += __shfl_xor_sync(0xffffffffu, s2, m);
            s3 += __shfl_xor_sync(0xffffffffu, s3, m);
        }
        if (lane < 4) {
            int bidx = blockIdx.x*16 + wm*4 + mt*2;
            int c = wn*16 + nt*8 + lane*2;
            *(float2*)&g_SDs[(size_t)bidx*64 + c]       = make_float2(s0, s1);
            *(float2*)&g_SDs[(size_t)(bidx + 1)*64 + c] = make_float2(s2, s3);
        }
    }
    __syncthreads();

    for (int ch = 0; ch < 8; ch++) {
        if (ch < 7) {
            pH = ((const uint4*)g_WpkH)[1536 + (ch+1)*512 + tid];
            pL = ((const uint4*)g_WpkL)[1536 + (ch+1)*512 + tid];
        }
        K1_ZERO(d);
        const uint32_t wcb = smb + K1_WC + (uint32_t)(ch & 1)*16384;
        gemm_k64(smb + K1_EHI, smb + K1_ELO, wcb, wcb + 8192, wm, wn, lane, d);
#pragma unroll
        for (int mt = 0; mt < 2; mt++)
#pragma unroll
        for (int nt = 0; nt < 2; nt++)
#pragma unroll
        for (int h = 0; h < 2; h++) {
            int r = wm*32 + mt*16 + (lane >> 2) + h*8;
            int c0 = wn*16 + nt*8 + (lane & 3)*2;
            float2 o;
            o.x = d[mt][nt][h*2];
            o.y = d[mt][nt][h*2 + 1];
            *(float2*)&g_AB[(size_t)(row0 + r)*512 + ch*64 + c0] = o;
        }
        if (ch < 7) {
            const uint32_t dstoff = K1_WC + (uint32_t)((ch+1) & 1)*16384;
            *(uint4*)(smc + dstoff + tid*16) = pH;
            *(uint4*)(smc + dstoff + 8192 + tid*16) = pL;
            __syncthreads();
        }
    }
}

// ===========================================================================
// K2v6: 76 KB smem -> 2 CTAs/SM for phase overlap. 1 batch (M=64)/superstep,
// 8 supersteps. X from g_AB gathers (no ABs smem); B operand via __ldg from
// tf32-prepacked g_Wt (L1-resident). Dedicated attp/atp/zvp (no aliases).
// ===========================================================================
#define SM2_XR   0        // 64 x 512 B (f32, XOR swizzle), rel X
#define SM2_XA   32768    // att X
#define SM2_PSM  65536    // [2][16] floats
#define SM2_ZVP  65664    // [2][64]
#define SM2_ZV   66176    // [64]
#define SM2_ATTP 66432    // [4][64]
#define SM2_ATP  67456    // [64]
#define SM2_A0P  67712    // [2] (+pad)
#define SMEM2_BYTES 77824 // padded to 76 KB: caps residency at 2 CTAs/SM

__global__ __launch_bounds__(512, 2)
void k2_kernel(const float* __restrict__ s,
               const float* __restrict__ W_rel0, const float* __restrict__ b_rel0,
               const float* __restrict__ W_rel1, const float* __restrict__ b_rel1,
               const float* __restrict__ W_rel2, const float* __restrict__ b_rel2,
               const float* __restrict__ W_att0, const float* __restrict__ b_att0,
               const float* __restrict__ W_att1, const float* __restrict__ b_att1,
               const float* __restrict__ W_att2, const float* __restrict__ b_att2,
               float* __restrict__ out)
{
    extern __shared__ char smc[];
    const int tid  = threadIdx.x;
    const int wid  = tid >> 5;
    const int lane = tid & 31;
    const uint32_t smb = smem_u32(smc);

    const int half = wid >> 3;          // 0 rel, 1 att
    const int wg = wid & 7;
    const int wm = wg & 1;              // 32-row group
    const int wn = wg >> 1;             // 16-col group (0..3)
    const int t2 = tid & 255;

    float* psmbuf = (float*)(smc + SM2_PSM);
    float* zvp    = (float*)(smc + SM2_ZVP);
    float* zv     = (float*)(smc + SM2_ZV);
    float* attp   = (float*)(smc + SM2_ATTP);
    float* atp    = (float*)(smc + SM2_ATP);
    float* a0p    = (float*)(smc + SM2_A0P);

    const float b2a = b_att2[0];

    // per-thread column constants
    const int c0 = wn*16 + (lane & 3)*2;
    float b1c[4], w2c[4];
    if (half) {
        b1c[0] = b_att1[c0];   b1c[1] = b_att1[c0+1];
        b1c[2] = b_att1[c0+8]; b1c[3] = b_att1[c0+9];
        w2c[0] = W_att2[c0];   w2c[1] = W_att2[c0+1];
        w2c[2] = W_att2[c0+8]; w2c[3] = W_att2[c0+9];
    } else {
        b1c[0] = b_rel1[c0];   b1c[1] = b_rel1[c0+1];
        b1c[2] = b_rel1[c0+8]; b1c[3] = b_rel1[c0+9];
        w2c[0] = w2c[1] = w2c[2] = w2c[3] = 0.f;
    }
    // X-build constants (k-quad = lane*4, own half)
    float4 wd4, bv4;
    if (half) {
        wd4 = *(const float4*)&W_att0[128*128 + lane*4];
        bv4 = *(const float4*)&b_att0[lane*4];
    } else {
        wd4 = *(const float4*)&W_rel0[128*128 + lane*4];
        bv4 = *(const float4*)&b_rel0[lane*4];
    }

    // B operand base in prepacked global W (L1-resident)
    const float* Wb = g_Wt + half*8192 + (wn*16 + (lane >> 2))*128 + (lane & 3);

    // prime psm[0]
    if (tid < 16)
        psmbuf[tid] = s[((size_t)(blockIdx.x*8) * 8 + (tid >> 1)) * 64 + (tid & 1)];
    __syncthreads();

    // GEMM addressing constants
    const uint32_t xbo = (uint32_t)(half ? SM2_XA : SM2_XR);
    const int r0l = wm*32 + ((lane >> 3) & 1)*8 + (lane & 7);
    const uint32_t abase = smb + xbo + (uint32_t)(r0l * 512);
    const uint32_t arsw  = (uint32_t)((lane & 7) << 4);
    const uint32_t aklane = (uint32_t)(((lane >> 4) & 1) << 4);
    const uint32_t xoff = ((uint32_t)(lane << 4)) ^ ((uint32_t)(wg << 4));

    for (int db = 0; db < 8; db++) {
        const int b = blockIdx.x * 8 + db;
        const int bn = blockIdx.x * 8 + ((db + 1) & 7);
        const float* psm = psmbuf + (db & 1) * 16;

        // early LDGs
        float psm_pf = 0.f;
        if (tid < 16)
            psm_pf = s[((size_t)bn * 8 + (tid >> 1)) * 64 + (tid & 1)];
        float sds = 0.f;
        if (half && t2 < 64)
            sds = g_SDs[(size_t)b*64 + t2];

        // ---- X build: own half, 8 iters, row = it*8 + wg, from g_AB ----
        const float* gbase = g_AB + (size_t)b * 4096 + half*256;
#pragma unroll
        for (int it = 0; it < 8; it++) {
            const int p_s = it*8 + wg;
            const int i = p_s >> 3, j = p_s & 7;
            const float dx = psm[2*i]     - psm[2*j];
            const float dy = psm[2*i + 1] - psm[2*j + 1];
            const float d = dx*dx + dy*dy;
            float4 A4 = *(const float4*)(gbase + i*512 + lane*4);
            float4 B4 = *(const float4*)(gbase + j*512 + 128 + lane*4);
            uint4 o;
            o.x = f2tf32(eluf(A4.x + B4.x + fmaf(d, wd4.x, bv4.x)));
            o.y = f2tf32(eluf(A4.y + B4.y + fmaf(d, wd4.y, bv4.y)));
            o.z = f2tf32(eluf(A4.z + B4.z + fmaf(d, wd4.z, bv4.z)));
            o.w = f2tf32(eluf(A4.w + B4.w + fmaf(d, wd4.w, bv4.w)));
            *(uint4*)(smc + xbo + (uint32_t)(p_s * 512) + xoff) = o;
        }
        if (!half) asm volatile("bar.sync 1, 256;" ::: "memory");
        else       asm volatile("bar.sync 2, 256;" ::: "memory");

        // ---- GEMM: tf32, 16 k-steps, warp tile 32x16 (mt=2) ----
        float d[2][2][4];
#pragma unroll
        for (int mt = 0; mt < 2; mt++)
#pragma unroll
            for (int nt = 0; nt < 2; nt++)
#pragma unroll
                for (int q = 0; q < 4; q++) d[mt][nt][q] = 0.f;

#pragma unroll
        for (int ks = 0; ks < 16; ks++) {
            const uint32_t kb = (uint32_t)(ks * 32);
            uint32_t b00 = __float_as_uint(__ldg(Wb + ks*8));
            uint32_t b01 = __float_as_uint(__ldg(Wb + ks*8 + 4));
            uint32_t b10 = __float_as_uint(__ldg(Wb + ks*8 + 1024));
            uint32_t b11 = __float_as_uint(__ldg(Wb + ks*8 + 1028));
#pragma unroll
            for (int mt = 0; mt < 2; mt++) {
                uint32_t a[4];
                ldsm4(a, abase + (uint32_t)(mt * 8192) + ((kb + aklane) ^ arsw));
                mma_tf32(d[mt][0], a, b00, b01);
                mma_tf32(d[mt][1], a, b10, b11);
            }
        }

        if (!half) {
            if (tid < 16) psmbuf[((db+1)&1)*16 + tid] = psm_pf;

            // elu in regs
#pragma unroll
            for (int mt = 0; mt < 2; mt++)
#pragma unroll
                for (int nt = 0; nt < 2; nt++)
#pragma unroll
                    for (int q = 0; q < 4; q++)
                        d[mt][nt][q] = eluf(d[mt][nt][q] + b1c[nt*2 + (q & 1)]);

            asm volatile("bar.sync 4, 512;" ::: "memory");   // wait atp

            // E3: rel scale by att + 32-row reduce -> zvp[wm]
            float at[2][2];
#pragma unroll
            for (int mt = 0; mt < 2; mt++) {
                at[mt][0] = atp[wm*32 + mt*16 + (lane >> 2)];
                at[mt][1] = atp[wm*32 + mt*16 + 8 + (lane >> 2)];
            }
            float z0 = 0.f, z1 = 0.f, z2 = 0.f, z3 = 0.f;
#pragma unroll
            for (int mt = 0; mt < 2; mt++) {
                z0 += d[mt][0][0]*at[mt][0] + d[mt][0][2]*at[mt][1];
                z1 += d[mt][0][1]*at[mt][0] + d[mt][0][3]*at[mt][1];
                z2 += d[mt][1][0]*at[mt][0] + d[mt][1][2]*at[mt][1];
                z3 += d[mt][1][1]*at[mt][0] + d[mt][1][3]*at[mt][1];
            }
#pragma unroll
            for (int m = 4; m <= 16; m <<= 1) {
                z0 += __shfl_xor_sync(0xffffffffu, z0, m);
                z1 += __shfl_xor_sync(0xffffffffu, z1, m);
                z2 += __shfl_xor_sync(0xffffffffu, z2, m);
                z3 += __shfl_xor_sync(0xffffffffu, z3, m);
            }
            if (lane < 4) {
                zvp[wm*64 + c0]     = z0;
                zvp[wm*64 + c0 + 1] = z1;
                zvp[wm*64 + c0 + 8] = z2;
                zvp[wm*64 + c0 + 9] = z3;
            }
            asm volatile("bar.sync 1, 256;" ::: "memory");   // zvp done (rel half)
            if (tid < 64) zv[tid] = zvp[tid] + zvp[64 + tid];
            asm volatile("bar.arrive 5, 512;" ::: "memory"); // zv ready
        } else {
            // E1: att partial dots -> attp[wn][row]
#pragma unroll
            for (int mt = 0; mt < 2; mt++) {
#pragma unroll
                for (int h = 0; h < 2; h++) {
                    float v0 = eluf(d[mt][0][h*2]     + b1c[0]);
                    float v1 = eluf(d[mt][0][h*2 + 1] + b1c[1]);
                    float v2 = eluf(d[mt][1][h*2]     + b1c[2]);
                    float v3 = eluf(d[mt][1][h*2 + 1] + b1c[3]);
                    float part = v0*w2c[0] + v1*w2c[1] + v2*w2c[2] + v3*w2c[3];
                    part += __shfl_xor_sync(0xffffffffu, part, 1);
                    part += __shfl_xor_sync(0xffffffffu, part, 2);
                    if ((lane & 3) == 0)
                        attp[wn*64 + wm*32 + mt*16 + h*8 + (lane >> 2)] = part;
                }
            }
            asm volatile("bar.sync 3, 256;" ::: "memory");

            // E2: finalize att (sigmoid, diag mask) -> atp + a0 warp partials
            if (t2 < 64) {
                const int i = t2 >> 3, j = t2 & 7;
                float a = attp[t2] + attp[64 + t2] + attp[128 + t2]
                        + attp[192 + t2] + b2a;
                float v = (i == j) ? 0.f : 1.f / (1.f + __expf(-a));
                atp[t2] = v;
                float w = v;
#pragma unroll
                for (int m = 1; m <= 16; m <<= 1)
                    w += __shfl_xor_sync(0xffffffffu, w, m);
                if (lane == 0) a0p[t2 >> 5] = w;
            }
            asm volatile("bar.arrive 4, 512;" ::: "memory"); // atp ready
            asm volatile("bar.sync 5, 512;" ::: "memory");   // wait zv

            // E4: output
            if (t2 < 64) {
                float a0 = a0p[0] + a0p[1];
                float o = zv[t2] + a0 * __ldg(&b_rel2[t2]) + sds;
#pragma unroll
                for (int k = 0; k < 64; k++)
                    o = fmaf(zv[k], __ldg(&W_rel2[k*64 + t2]), o);
                out[(size_t)b * 64 + t2] = o;
            }
        }
        __syncthreads();
    }
}

// ---------------------------------------------------------------------------
extern "C" void kernel_launch(void* const* d_in, const int* in_sizes, int n_in,
                              void* d_out, int out_size)
{
    const float* s       = (const float*)d_in[0];
    const float* W_enc   = (const float*)d_in[1];
    const float* b_enc   = (const float*)d_in[2];
    const float* W_self0 = (const float*)d_in[3];
    const float* b_self0 = (const float*)d_in[4];
    const float* W_self1 = (const float*)d_in[5];
    const float* b_self1 = (const float*)d_in[6];
    const float* W_rel0  = (const float*)d_in[7];
    const float* b_rel0  = (const float*)d_in[8];
    const float* W_rel1  = (const float*)d_in[9];
    const float* b_rel1  = (const float*)d_in[10];
    const float* W_rel2  = (const float*)d_in[11];
    const float* b_rel2  = (const float*)d_in[12];
    const float* W_att0  = (const float*)d_in[13];
    const float* b_att0  = (const float*)d_in[14];
    const float* W_att1  = (const float*)d_in[15];
    const float* b_att1  = (const float*)d_in[16];
    const float* W_att2  = (const float*)d_in[17];
    const float* b_att2  = (const float*)d_in[18];
    float* out = (float*)d_out;

    cudaFuncSetAttribute(k1_kernel, cudaFuncAttributeMaxDynamicSharedMemorySize, SMEM1_BYTES);
    cudaFuncSetAttribute(k2_kernel, cudaFuncAttributeMaxDynamicSharedMemorySize, SMEM2_BYTES);

    k0_kernel<<<152, 256>>>(W_enc, W_self0, W_self1, W_rel0, W_att0, W_rel1, W_att1);
    k1_kernel<<<ROWS/128, 512, SMEM1_BYTES>>>(s, b_enc, b_self0, b_self1);
    k2_kernel<<<BATCH/8, 512, SMEM2_BYTES>>>(s, W_rel0, b_rel0, W_rel1, b_rel1,
                                             W_rel2, b_rel2, W_att0, b_att0,
                                             W_att1, b_att1, W_att2, b_att2, out);
}

// round 15
// speedup vs baseline: 1.6028x; 1.6028x over previous
#include <cuda_runtime.h>
#include <stdint.h>
#include <math.h>

#define BATCH 8192
#define ROWS  65536

// Scratch (static device globals; allocation-free per harness rules)
__device__ float g_AB[(size_t)ROWS * 512];  // per row: [A_rel(128)|B_rel(128)|A_att(128)|B_att(128)]
__device__ float g_SD[(size_t)ROWS * 64];   // self_dyn per (b,i)
// Prepacked k1 weights, bf16 hi/lo, swizzled smem-image layout.
__device__ __align__(16) uint16_t g_WpkH[45056];
__device__ __align__(16) uint16_t g_WpkL[45056];

__device__ __forceinline__ float eluf(float x) {
    return x > 0.f ? x : (__expf(x) - 1.f);
}
__device__ __forceinline__ uint32_t smem_u32(const void* p) {
    uint32_t a;
    asm("{ .reg .u64 t; cvta.to.shared.u64 t, %1; cvt.u32.u64 %0, t; }" : "=r"(a) : "l"(p));
    return a;
}
// split x0,x1 (memory order: x0 first) into packed bf16 hi pair + lo pair
__device__ __forceinline__ void split2(float x0, float x1, uint32_t& hi, uint32_t& lo) {
    uint32_t h;
    asm("cvt.rn.bf16x2.f32 %0, %1, %2;" : "=r"(h) : "f"(x1), "f"(x0));
    float h0 = __uint_as_float(h << 16);
    float h1 = __uint_as_float(h & 0xffff0000u);
    float l0 = x0 - h0, l1 = x1 - h1;
    uint32_t l;
    asm("cvt.rn.bf16x2.f32 %0, %1, %2;" : "=r"(l) : "f"(l1), "f"(l0));
    hi = h; lo = l;
}
__device__ __forceinline__ uint32_t f2tf32(float x) {
    uint32_t r;
    asm("cvt.rna.tf32.f32 %0, %1;" : "=r"(r) : "f"(x));
    return r;
}
__device__ __forceinline__ void ldsm4(uint32_t r[4], uint32_t addr) {
    asm volatile("ldmatrix.sync.aligned.m8n8.x4.shared.b16 {%0,%1,%2,%3}, [%4];"
        : "=r"(r[0]), "=r"(r[1]), "=r"(r[2]), "=r"(r[3]) : "r"(addr));
}
__device__ __forceinline__ void mma16816(float d[4], const uint32_t a[4],
                                         uint32_t b0, uint32_t b1) {
    asm volatile("mma.sync.aligned.m16n8k16.row.col.f32.bf16.bf16.f32 "
        "{%0,%1,%2,%3}, {%4,%5,%6,%7}, {%8,%9}, {%0,%1,%2,%3};"
        : "+f"(d[0]), "+f"(d[1]), "+f"(d[2]), "+f"(d[3])
        : "r"(a[0]), "r"(a[1]), "r"(a[2]), "r"(a[3]), "r"(b0), "r"(b1));
}
__device__ __forceinline__ void mma_tf32(float d[4], const uint32_t a[4],
                                         uint32_t b0, uint32_t b1) {
    asm volatile("mma.sync.aligned.m16n8k8.row.col.f32.tf32.tf32.f32 "
        "{%0,%1,%2,%3}, {%4,%5,%6,%7}, {%8,%9}, {%0,%1,%2,%3};"
        : "+f"(d[0]), "+f"(d[1]), "+f"(d[2]), "+f"(d[3])
        : "r"(a[0]), "r"(a[1]), "r"(a[2]), "r"(a[3]), "r"(b0), "r"(b1));
}

// ---------------------------------------------------------------------------
// K0: prepack k1 weights into bf16 hi/lo swizzled smem images. (R10 verbatim)
// ---------------------------------------------------------------------------
__device__ __forceinline__ float catw(const float* Wr, const float* Wa, int k, int g) {
    if (g < 128) return Wr[k*128 + g];
    if (g < 256) return Wr[(64+k)*128 + (g-128)];
    if (g < 384) return Wa[k*128 + (g-256)];
    return Wa[(64+k)*128 + (g-384)];
}

__global__ void k0_kernel(const float* __restrict__ W_enc,
                          const float* __restrict__ W_self0,
                          const float* __restrict__ W_self1,
                          const float* __restrict__ W_rel0,
                          const float* __restrict__ W_att0)
{
    int e = blockIdx.x * 256 + threadIdx.x;
    if (e >= 22528) return;
    int tile = e >> 11;
    int idx = e & 2047;
    int n = idx & 63, k0 = (idx >> 6) * 2;
    float v0, v1;
    if (tile == 0)      { v0 = W_enc[k0*64+n];   v1 = W_enc[(k0+1)*64+n]; }
    else if (tile == 1) { v0 = W_self0[k0*64+n]; v1 = W_self0[(k0+1)*64+n]; }
    else if (tile == 2) { v0 = W_self1[k0*64+n]; v1 = W_self1[(k0+1)*64+n]; }
    else {
        int g = (tile - 3) * 64 + n;
        v0 = catw(W_rel0, W_att0, k0, g);
        v1 = catw(W_rel0, W_att0, k0 + 1, g);
    }
    uint32_t hb, lb;
    split2(v0, v1, hb, lb);
    uint32_t off16 = (uint32_t)(tile*4096 + n*64 + (((k0>>3)*8) ^ ((n&7)*8)) + (k0&7));
    *(uint32_t*)((char*)g_WpkH + off16*2) = hb;
    *(uint32_t*)((char*)g_WpkL + off16*2) = lb;
}

// ---------------------------------------------------------------------------
// K1v2: R10 verbatim + bofs grid offset.
// ---------------------------------------------------------------------------
#define K1_XHI 0
#define K1_XLO 16384
#define K1_EHI 32768
#define K1_ELO 49152
#define K1_WSH 65536
#define K1_WSL 90112
#define K1_WC  114688
#define K1_S01 147456
#define SMEM1_BYTES 148480

__device__ __forceinline__ void gemm_k64(uint32_t AH, uint32_t AL,
                                         uint32_t BH, uint32_t BL,
                                         int wm, int wn, int lane, float d[2][2][4])
{
    const int nloc = wn*16 + (lane & 7) + ((lane >> 4) << 3);
    const int nsw  = (lane & 7) * 16;
    const int bkc0 = (lane >> 3) & 1;
    const int rloc0 = wm*32 + (lane & 15);
    const int rsw  = (lane & 7) * 16;
    const int akc0 = lane >> 4;
#pragma unroll
    for (int ks = 0; ks < 4; ks++) {
        uint32_t bh[4], bl[4];
        {
            uint32_t boff = (uint32_t)(nloc*128 + (((ks*2 + bkc0)*16) ^ nsw));
            ldsm4(bh, BH + boff);
            ldsm4(bl, BL + boff);
        }
#pragma unroll
        for (int mt = 0; mt < 2; mt++) {
            uint32_t aoff = (uint32_t)((rloc0 + mt*16)*128 + (((ks*2 + akc0)*16) ^ rsw));
            uint32_t ah[4], al[4];
            ldsm4(ah, AH + aoff);
            ldsm4(al, AL + aoff);
            mma16816(d[mt][0], ah, bh[0], bh[1]);
            mma16816(d[mt][1], ah, bh[2], bh[3]);
            mma16816(d[mt][0], al, bh[0], bh[1]);
            mma16816(d[mt][1], al, bh[2], bh[3]);
            mma16816(d[mt][0], ah, bl[0], bl[1]);
            mma16816(d[mt][1], ah, bl[2], bl[3]);
        }
    }
}
#define K1_ZERO(d) { _Pragma("unroll") for (int _m=0;_m<2;_m++) _Pragma("unroll") for (int _n=0;_n<2;_n++) _Pragma("unroll") for (int _q=0;_q<4;_q++) (d)[_m][_n][_q]=0.f; }

__global__ __launch_bounds__(512, 1)
void k1_kernel(const float* __restrict__ s,
               const float* __restrict__ b_enc,
               const float* __restrict__ b_self0,
               const float* __restrict__ b_self1,
               int bofs)
{
    extern __shared__ char smc[];
    const uint32_t smb = smem_u32(smc);
    const int tid = threadIdx.x, lane = tid & 31, wid = tid >> 5;
    const int wm = wid & 3, wn = wid >> 2;
    const int row0 = (blockIdx.x + bofs) * 128;
    float* s01 = (float*)(smc + K1_S01);

    {
        const uint4* srcH = (const uint4*)g_WpkH;
        const uint4* srcL = (const uint4*)g_WpkL;
#pragma unroll
        for (int q = 0; q < 3; q++) {
            ((uint4*)(smc + K1_WSH))[tid + q*512] = srcH[tid + q*512];
            ((uint4*)(smc + K1_WSL))[tid + q*512] = srcL[tid + q*512];
        }
    }
    uint4 pH = ((const uint4*)g_WpkH)[1536 + tid];
    uint4 pL = ((const uint4*)g_WpkL)[1536 + tid];

#pragma unroll
    for (int it = 0; it < 4; it++) {
        int idx = tid + it*512;
        int r = idx >> 4, kq = idx & 15, k0 = kq*4;
        float4 v = *(const float4*)(s + (size_t)(row0 + r)*64 + k0);
        if (kq == 0) { s01[r*2] = v.x; s01[r*2+1] = v.y; }
        uint32_t h0, l0, h1, l1;
        split2(v.x, v.y, h0, l0);
        split2(v.z, v.w, h1, l1);
        uint32_t off = (uint32_t)(r*128 + (((k0>>3)*16) ^ ((r&7)*16)) + (k0&7)*2);
        *(uint2*)(smc + K1_XHI + off) = make_uint2(h0, h1);
        *(uint2*)(smc + K1_XLO + off) = make_uint2(l0, l1);
    }

    const int c0b = wn*16 + (lane & 3)*2;
    float be[4], bs0[4], bs1[4];
    be[0]  = b_enc[c0b];    be[1]  = b_enc[c0b+1];
    be[2]  = b_enc[c0b+8];  be[3]  = b_enc[c0b+9];
    bs0[0] = b_self0[c0b];   bs0[1] = b_self0[c0b+1];
    bs0[2] = b_self0[c0b+8]; bs0[3] = b_self0[c0b+9];
    bs1[0] = b_self1[c0b];   bs1[1] = b_self1[c0b+1];
    bs1[2] = b_self1[c0b+8]; bs1[3] = b_self1[c0b+9];
    __syncthreads();

    float d[2][2][4];

    K1_ZERO(d);
    gemm_k64(smb + K1_XHI, smb + K1_XLO, smb + K1_WSH, smb + K1_WSL, wm, wn, lane, d);
#pragma unroll
    for (int mt = 0; mt < 2; mt++)
#pragma unroll
    for (int nt = 0; nt < 2; nt++)
#pragma unroll
    for (int h = 0; h < 2; h++) {
        int r = wm*32 + mt*16 + (lane >> 2) + h*8;
        int c0 = wn*16 + nt*8 + (lane & 3)*2;
        float v0 = d[mt][nt][h*2]     + be[nt*2];
        float v1 = d[mt][nt][h*2 + 1] + be[nt*2 + 1];
        if (c0 == 0) { v0 = s01[r*2]; v1 = s01[r*2+1]; }
        uint32_t hb, lb;
        split2(v0, v1, hb, lb);
        uint32_t off = (uint32_t)(r*128 + (((c0>>3)*16) ^ ((r&7)*16)) + (c0&7)*2);
        *(uint32_t*)(smc + K1_EHI + off) = hb;
        *(uint32_t*)(smc + K1_ELO + off) = lb;
    }
    __syncthreads();

    K1_ZERO(d);
    gemm_k64(smb + K1_EHI, smb + K1_ELO, smb + K1_WSH + 8192, smb + K1_WSL + 8192,
             wm, wn, lane, d);
    float hf[2][2][4];
#pragma unroll
    for (int mt = 0; mt < 2; mt++)
#pragma unroll
    for (int nt = 0; nt < 2; nt++)
#pragma unroll
    for (int h = 0; h < 2; h++) {
        int r = wm*32 + mt*16 + (lane >> 2) + h*8;
        int c0 = wn*16 + nt*8 + (lane & 3)*2;
        float v0 = eluf(d[mt][nt][h*2]     + bs0[nt*2]);
        float v1 = eluf(d[mt][nt][h*2 + 1] + bs0[nt*2 + 1]);
        hf[mt][nt][h*2] = v0; hf[mt][nt][h*2+1] = v1;
        uint32_t hb, lb;
        split2(v0, v1, hb, lb);
        uint32_t off = (uint32_t)(r*128 + (((c0>>3)*16) ^ ((r&7)*16)) + (c0&7)*2);
        *(uint32_t*)(smc + K1_XHI + off) = hb;
        *(uint32_t*)(smc + K1_XLO + off) = lb;
    }
    __syncthreads();

    *(uint4*)(smc + K1_WC + tid*16) = pH;
    *(uint4*)(smc + K1_WC + 8192 + tid*16) = pL;

    K1_ZERO(d);
    gemm_k64(smb + K1_XHI, smb + K1_XLO, smb + K1_WSH + 16384, smb + K1_WSL + 16384,
             wm, wn, lane, d);
#pragma unroll
    for (int mt = 0; mt < 2; mt++)
#pragma unroll
    for (int nt = 0; nt < 2; nt++)
#pragma unroll
    for (int h = 0; h < 2; h++) {
        int r = wm*32 + mt*16 + (lane >> 2) + h*8;
        int c0 = wn*16 + nt*8 + (lane & 3)*2;
        float2 o;
        o.x = d[mt][nt][h*2]     + bs1[nt*2]     + hf[mt][nt][h*2];
        o.y = d[mt][nt][h*2 + 1] + bs1[nt*2 + 1] + hf[mt][nt][h*2 + 1];
        *(float2*)&g_SD[(size_t)(row0 + r)*64 + c0] = o;
    }
    __syncthreads();

    for (int ch = 0; ch < 8; ch++) {
        if (ch < 7) {
            pH = ((const uint4*)g_WpkH)[1536 + (ch+1)*512 + tid];
            pL = ((const uint4*)g_WpkL)[1536 + (ch+1)*512 + tid];
        }
        K1_ZERO(d);
        const uint32_t wcb = smb + K1_WC + (uint32_t)(ch & 1)*16384;
        gemm_k64(smb + K1_EHI, smb + K1_ELO, wcb, wcb + 8192, wm, wn, lane, d);
#pragma unroll
        for (int mt = 0; mt < 2; mt++)
#pragma unroll
        for (int nt = 0; nt < 2; nt++)
#pragma unroll
        for (int h = 0; h < 2; h++) {
            int r = wm*32 + mt*16 + (lane >> 2) + h*8;
            int c0 = wn*16 + nt*8 + (lane & 3)*2;
            float2 o;
            o.x = d[mt][nt][h*2];
            o.y = d[mt][nt][h*2 + 1];
            *(float2*)&g_AB[(size_t)(row0 + r)*512 + ch*64 + c0] = o;
        }
        if (ch < 7) {
            const uint32_t dstoff = K1_WC + (uint32_t)((ch+1) & 1)*16384;
            *(uint4*)(smc + dstoff + tid*16) = pH;
            *(uint4*)(smc + dstoff + 8192 + tid*16) = pL;
            __syncthreads();
        }
    }
}

// ===========================================================================
// K2v4b: R10 verbatim (best-known-good, 371.2us run) + bofs grid offset.
// ===========================================================================
#define SM2_XR   0
#define SM2_XA   65536
#define SM2_WR   131072
#define SM2_WA   163840
#define SM2_ABS  196608
#define SM2_WD   229376
#define SMEM2_BYTES 230400

__global__ __launch_bounds__(512, 1)
void k2_kernel(const float* __restrict__ s,
               const float* __restrict__ W_rel0, const float* __restrict__ b_rel0,
               const float* __restrict__ W_rel1, const float* __restrict__ b_rel1,
               const float* __restrict__ W_rel2, const float* __restrict__ b_rel2,
               const float* __restrict__ W_att0, const float* __restrict__ b_att0,
               const float* __restrict__ W_att1, const float* __restrict__ b_att1,
               const float* __restrict__ W_att2, const float* __restrict__ b_att2,
               float* __restrict__ out, int bofs)
{
    extern __shared__ char smc[];
    const int tid  = threadIdx.x;
    const int wid  = tid >> 5;
    const int lane = tid & 31;
    const uint32_t smb = smem_u32(smc);
    const int bx = blockIdx.x + bofs;

    const int half = wid >> 3;
    const int wg = wid & 7;
    const int wm = wg & 1;
    const int wn = wg >> 1;
    const int t2 = tid & 255;

    float* psmbuf = (float*)(smc + SM2_WD);
    float* b2r_s  = (float*)(smc + SM2_WD + 256);
    float* zv     = (float*)(smc + SM2_WD + 512);
    float* ABsf   = (float*)(smc + SM2_ABS);

    for (int idx = tid; idx < 8192; idx += 512) {
        int n = idx & 63, k = idx >> 6;
        uint32_t off = (uint32_t)(n*512 + ((k*4) ^ ((n&7)*16)));
        *(uint32_t*)(smc + SM2_WR + off) = f2tf32(W_rel1[k*64 + n]);
        *(uint32_t*)(smc + SM2_WA + off) = f2tf32(W_att1[k*64 + n]);
    }
    if (tid < 64) b2r_s[tid] = b_rel2[tid];
    const float b2a = b_att2[0];

    const int c0 = wn*16 + (lane & 3)*2;
    float b1c[4], w2c[4];
    if (half) {
        b1c[0] = b_att1[c0];   b1c[1] = b_att1[c0+1];
        b1c[2] = b_att1[c0+8]; b1c[3] = b_att1[c0+9];
        w2c[0] = W_att2[c0];   w2c[1] = W_att2[c0+1];
        w2c[2] = W_att2[c0+8]; w2c[3] = W_att2[c0+9];
    } else {
        b1c[0] = b_rel1[c0];   b1c[1] = b_rel1[c0+1];
        b1c[2] = b_rel1[c0+8]; b1c[3] = b_rel1[c0+9];
        w2c[0] = w2c[1] = w2c[2] = w2c[3] = 0.f;
    }
    float4 wd4, bv4;
    if (half) {
        wd4 = *(const float4*)&W_att0[128*128 + lane*4];
        bv4 = *(const float4*)&b_att0[lane*4];
    } else {
        wd4 = *(const float4*)&W_rel0[128*128 + lane*4];
        bv4 = *(const float4*)&b_rel0[lane*4];
    }

    {
        const float4* src = (const float4*)(g_AB + (size_t)(bx*8) * 4096);
#pragma unroll
        for (int q = 0; q < 4; q++) ((float4*)ABsf)[tid + q*512] = src[tid + q*512];
        if (tid < 32)
            psmbuf[tid] = s[((size_t)(bx*8 + (tid>>4)) * 8 + ((tid>>1)&7)) * 64 + (tid & 1)];
    }
    __syncthreads();

    const uint32_t xbo = (uint32_t)(half ? SM2_XA : SM2_XR);
    const int r0l = wm*64 + ((lane >> 3) & 1)*8 + (lane & 7);
    const uint32_t abase = smb + xbo + (uint32_t)(r0l * 512);
    const uint32_t arsw  = (uint32_t)((r0l & 7) << 4);
    const uint32_t aklane = (uint32_t)(((lane >> 4) & 1) << 4);
    const uint32_t wboff = (uint32_t)(half ? SM2_WA : SM2_WR)
                         + (uint32_t)((wn*16 + (lane >> 2)) * 512);
    const uint32_t bnsw = (uint32_t)((lane >> 2) << 4);
    const uint32_t bklo = (uint32_t)((lane & 3) << 2);
    const uint32_t xoff = ((uint32_t)(lane << 4)) ^ ((uint32_t)((wid & 7) << 4));

    for (int db = 0; db < 4; db++) {
        const int b0 = bx * 8 + db * 2;
        const int nb = (db + 1) & 3;
        const int b0n = bx * 8 + nb * 2;
        const float* psm = psmbuf + (db & 1) * 32;

        float4 pf[4];
        {
            const float* src = g_AB + (size_t)b0n * 4096;
#pragma unroll
            for (int q = 0; q < 4; q++) {
                int item = t2 + q*256;
                int row = item >> 6, f4 = (item & 63) + half*64;
                pf[q] = *(const float4*)(src + row*512 + f4*4);
            }
        }
        float psm_pf = 0.f;
        if (tid < 32)
            psm_pf = s[((size_t)(b0n + (tid>>4)) * 8 + ((tid>>1)&7)) * 64 + (tid & 1)];
        float gsd[8];
        if (half && t2 < 128) {
            int bb = t2 >> 6, c = t2 & 63;
#pragma unroll
            for (int i = 0; i < 8; i++)
                gsd[i] = g_SD[(size_t)((b0 + bb)*8 + i) * 64 + c];
        }

#pragma unroll
        for (int it = 0; it < 16; it++) {
            const int p_s = it*8 + (wid & 7);
            const int bbi = p_s >> 6, p = p_s & 63, i = p >> 3, j = p & 7;
            const float dx = psm[bbi*16 + 2*i]     - psm[bbi*16 + 2*j];
            const float dy = psm[bbi*16 + 2*i + 1] - psm[bbi*16 + 2*j + 1];
            const float d = dx*dx + dy*dy;
            const float* base = ABsf + bbi*4096 + half*256;
            float4 A4 = *(const float4*)(base + i*512 + lane*4);
            float4 B4 = *(const float4*)(base + j*512 + 128 + lane*4);
            uint4 o;
            o.x = f2tf32(eluf(A4.x + B4.x + fmaf(d, wd4.x, bv4.x)));
            o.y = f2tf32(eluf(A4.y + B4.y + fmaf(d, wd4.y, bv4.y)));
            o.z = f2tf32(eluf(A4.z + B4.z + fmaf(d, wd4.z, bv4.z)));
            o.w = f2tf32(eluf(A4.w + B4.w + fmaf(d, wd4.w, bv4.w)));
            *(uint4*)(smc + xbo + (uint32_t)(p_s * 512) + xoff) = o;
        }
        if (!half) asm volatile("bar.sync 1, 256;" ::: "memory");
        else       asm volatile("bar.sync 2, 256;" ::: "memory");

        float d[4][2][4];
#pragma unroll
        for (int mt = 0; mt < 4; mt++)
#pragma unroll
            for (int nt = 0; nt < 2; nt++)
#pragma unroll
                for (int q = 0; q < 4; q++) d[mt][nt][q] = 0.f;

#pragma unroll
        for (int ks = 0; ks < 16; ks++) {
            const uint32_t kb = (uint32_t)(ks * 32);
            uint32_t b00 = *(const uint32_t*)(smc + wboff + ((kb + bklo) ^ bnsw));
            uint32_t b01 = *(const uint32_t*)(smc + wboff + ((kb + bklo + 16) ^ bnsw));
            uint32_t b10 = *(const uint32_t*)(smc + wboff + 4096 + ((kb + bklo) ^ bnsw));
            uint32_t b11 = *(const uint32_t*)(smc + wboff + 4096 + ((kb + bklo + 16) ^ bnsw));
#pragma unroll
            for (int mt = 0; mt < 4; mt++) {
                uint32_t a[4];
                ldsm4(a, abase + (uint32_t)(mt * 8192) + ((kb + aklane) ^ arsw));
                mma_tf32(d[mt][0], a, b00, b01);
                mma_tf32(d[mt][1], a, b10, b11);
            }
        }

        if (!half) {
#pragma unroll
            for (int q = 0; q < 4; q++) {
                int item = t2 + q*256;
                int row = item >> 6, f4 = item & 63;
                *(float4*)(ABsf + row*512 + f4*4) = pf[q];
            }
            if (tid < 32) psmbuf[((db+1)&1)*32 + tid] = psm_pf;

#pragma unroll
            for (int mt = 0; mt < 4; mt++)
#pragma unroll
                for (int nt = 0; nt < 2; nt++)
#pragma unroll
                    for (int q = 0; q < 4; q++)
                        d[mt][nt][q] = eluf(d[mt][nt][q] + b1c[nt*2 + (q & 1)]);

            asm volatile("bar.sync 4, 512;" ::: "memory");

            float at[4][2];
#pragma unroll
            for (int mt = 0; mt < 4; mt++) {
                at[mt][0] = ABsf[1280 + wm*64 + mt*16 + (lane >> 2)];
                at[mt][1] = ABsf[1280 + wm*64 + mt*16 + 8 + (lane >> 2)];
            }
            float z0 = 0.f, z1 = 0.f, z2 = 0.f, z3 = 0.f;
#pragma unroll
            for (int mt = 0; mt < 4; mt++) {
                z0 += d[mt][0][0]*at[mt][0] + d[mt][0][2]*at[mt][1];
                z1 += d[mt][0][1]*at[mt][0] + d[mt][0][3]*at[mt][1];
                z2 += d[mt][1][0]*at[mt][0] + d[mt][1][2]*at[mt][1];
                z3 += d[mt][1][1]*at[mt][0] + d[mt][1][3]*at[mt][1];
            }
#pragma unroll
            for (int m = 4; m <= 16; m <<= 1) {
                z0 += __shfl_xor_sync(0xffffffffu, z0, m);
                z1 += __shfl_xor_sync(0xffffffffu, z1, m);
                z2 += __shfl_xor_sync(0xffffffffu, z2, m);
                z3 += __shfl_xor_sync(0xffffffffu, z3, m);
            }
            if (lane < 4) {
                zv[wm*64 + c0]     = z0;
                zv[wm*64 + c0 + 1] = z1;
                zv[wm*64 + c0 + 8] = z2;
                zv[wm*64 + c0 + 9] = z3;
            }
            asm volatile("bar.arrive 5, 512;" ::: "memory");
        } else {
#pragma unroll
            for (int mt = 0; mt < 4; mt++) {
#pragma unroll
                for (int h = 0; h < 2; h++) {
                    float v0 = eluf(d[mt][0][h*2]     + b1c[0]);
                    float v1 = eluf(d[mt][0][h*2 + 1] + b1c[1]);
                    float v2 = eluf(d[mt][1][h*2]     + b1c[2]);
                    float v3 = eluf(d[mt][1][h*2 + 1] + b1c[3]);
                    float part = v0*w2c[0] + v1*w2c[1] + v2*w2c[2] + v3*w2c[3];
                    part += __shfl_xor_sync(0xffffffffu, part, 1);
                    part += __shfl_xor_sync(0xffffffffu, part, 2);
                    if ((lane & 3) == 0) {
                        int idx = wn*128 + wm*64 + mt*16 + h*8 + (lane >> 2);
                        ABsf[(idx >> 8)*512 + 256 + (idx & 255)] = part;
                    }
                }
            }
            asm volatile("bar.sync 3, 256;" ::: "memory");

            if (t2 < 128) {
                const int p = t2 & 63, i = p >> 3, j = p & 7;
                float a = ABsf[256 + t2] + ABsf[384 + t2]
                        + ABsf[768 + t2] + ABsf[896 + t2] + b2a;
                ABsf[1280 + t2] = (i == j) ? 0.f : 1.f / (1.f + __expf(-a));
            }
            asm volatile("bar.arrive 4, 512;" ::: "memory");
            asm volatile("bar.sync 5, 512;" ::: "memory");

            if (t2 < 128) {
                const int bb = t2 >> 6, c = t2 & 63;
                float a0 = 0.f;
#pragma unroll
                for (int p = 0; p < 64; p++) a0 += ABsf[1280 + bb*64 + p];
                float sd = gsd[0] + gsd[1] + gsd[2] + gsd[3]
                         + gsd[4] + gsd[5] + gsd[6] + gsd[7];
                float o = zv[t2] + a0 * b2r_s[c] + sd;
#pragma unroll
                for (int k = 0; k < 64; k++)
                    o = fmaf(zv[bb*64 + k], W_rel2[k*64 + c], o);
                out[(size_t)(b0 + bb) * 64 + c] = o;
            }
            asm volatile("bar.sync 3, 256;" ::: "memory");

#pragma unroll
            for (int q = 0; q < 4; q++) {
                int item = t2 + q*256;
                int row = item >> 6, f4 = 64 + (item & 63);
                *(float4*)(ABsf + row*512 + f4*4) = pf[q];
            }
        }
        __syncthreads();
    }
}

// ---------------------------------------------------------------------------
// Pipelined launch: 4 chunks, k1 on stream 0, k2 on forked stream B.
// k2 chunk c depends only on k1 chunk c (batch-aligned).
// ---------------------------------------------------------------------------
extern "C" void kernel_launch(void* const* d_in, const int* in_sizes, int n_in,
                              void* d_out, int out_size)
{
    const float* s       = (const float*)d_in[0];
    const float* W_enc   = (const float*)d_in[1];
    const float* b_enc   = (const float*)d_in[2];
    const float* W_self0 = (const float*)d_in[3];
    const float* b_self0 = (const float*)d_in[4];
    const float* W_self1 = (const float*)d_in[5];
    const float* b_self1 = (const float*)d_in[6];
    const float* W_rel0  = (const float*)d_in[7];
    const float* b_rel0  = (const float*)d_in[8];
    const float* W_rel1  = (const float*)d_in[9];
    const float* b_rel1  = (const float*)d_in[10];
    const float* W_rel2  = (const float*)d_in[11];
    const float* b_rel2  = (const float*)d_in[12];
    const float* W_att0  = (const float*)d_in[13];
    const float* b_att0  = (const float*)d_in[14];
    const float* W_att1  = (const float*)d_in[15];
    const float* b_att1  = (const float*)d_in[16];
    const float* W_att2  = (const float*)d_in[17];
    const float* b_att2  = (const float*)d_in[18];
    float* out = (float*)d_out;

    cudaFuncSetAttribute(k1_kernel, cudaFuncAttributeMaxDynamicSharedMemorySize, SMEM1_BYTES);
    cudaFuncSetAttribute(k2_kernel, cudaFuncAttributeMaxDynamicSharedMemorySize, SMEM2_BYTES);

    cudaStream_t sB;
    cudaStreamCreateWithFlags(&sB, cudaStreamNonBlocking);
    cudaEvent_t evC[4], evJ;
    for (int c = 0; c < 4; c++) cudaEventCreateWithFlags(&evC[c], cudaEventDisableTiming);
    cudaEventCreateWithFlags(&evJ, cudaEventDisableTiming);

    k0_kernel<<<88, 256>>>(W_enc, W_self0, W_self1, W_rel0, W_att0);
    for (int c = 0; c < 4; c++) {
        k1_kernel<<<128, 512, SMEM1_BYTES>>>(s, b_enc, b_self0, b_self1, c*128);
        cudaEventRecord(evC[c], 0);
        cudaStreamWaitEvent(sB, evC[c], 0);
        k2_kernel<<<256, 512, SMEM2_BYTES, sB>>>(s, W_rel0, b_rel0, W_rel1, b_rel1,
                                                 W_rel2, b_rel2, W_att0, b_att0,
                                                 W_att1, b_att1, W_att2, b_att2,
                                                 out, c*256);
    }
    cudaEventRecord(evJ, sB);
    cudaStreamWaitEvent(0, evJ, 0);
}

// round 16
// speedup vs baseline: 1.7703x; 1.1045x over previous
#include <cuda_runtime.h>
#include <stdint.h>
#include <math.h>

#define BATCH 8192
#define ROWS  65536

// Scratch (static device globals; allocation-free per harness rules)
__device__ float g_AB[(size_t)ROWS * 512];  // per row: [A_rel(128)|B_rel(128)|A_att(128)|B_att(128)]
__device__ float g_SD[(size_t)ROWS * 64];   // self_dyn per (b,i)
// Prepacked k1 weights, bf16 hi/lo, swizzled smem-image layout.
__device__ __align__(16) uint16_t g_WpkH[45056];
__device__ __align__(16) uint16_t g_WpkL[45056];
// Prepacked k2 W_rel1/W_att1, tf32, exact swizzled smem image (uint32 elems).
__device__ __align__(16) uint32_t g_WtImg[2 * 8192];

__device__ __forceinline__ float eluf(float x) {
    return x > 0.f ? x : (__expf(x) - 1.f);
}
__device__ __forceinline__ uint32_t smem_u32(const void* p) {
    uint32_t a;
    asm("{ .reg .u64 t; cvta.to.shared.u64 t, %1; cvt.u32.u64 %0, t; }" : "=r"(a) : "l"(p));
    return a;
}
// split x0,x1 (memory order: x0 first) into packed bf16 hi pair + lo pair
__device__ __forceinline__ void split2(float x0, float x1, uint32_t& hi, uint32_t& lo) {
    uint32_t h;
    asm("cvt.rn.bf16x2.f32 %0, %1, %2;" : "=r"(h) : "f"(x1), "f"(x0));
    float h0 = __uint_as_float(h << 16);
    float h1 = __uint_as_float(h & 0xffff0000u);
    float l0 = x0 - h0, l1 = x1 - h1;
    uint32_t l;
    asm("cvt.rn.bf16x2.f32 %0, %1, %2;" : "=r"(l) : "f"(l1), "f"(l0));
    hi = h; lo = l;
}
__device__ __forceinline__ uint32_t f2tf32(float x) {
    uint32_t r;
    asm("cvt.rna.tf32.f32 %0, %1;" : "=r"(r) : "f"(x));
    return r;
}
__device__ __forceinline__ void ldsm4(uint32_t r[4], uint32_t addr) {
    asm volatile("ldmatrix.sync.aligned.m8n8.x4.shared.b16 {%0,%1,%2,%3}, [%4];"
        : "=r"(r[0]), "=r"(r[1]), "=r"(r[2]), "=r"(r[3]) : "r"(addr));
}
__device__ __forceinline__ void mma16816(float d[4], const uint32_t a[4],
                                         uint32_t b0, uint32_t b1) {
    asm volatile("mma.sync.aligned.m16n8k16.row.col.f32.bf16.bf16.f32 "
        "{%0,%1,%2,%3}, {%4,%5,%6,%7}, {%8,%9}, {%0,%1,%2,%3};"
        : "+f"(d[0]), "+f"(d[1]), "+f"(d[2]), "+f"(d[3])
        : "r"(a[0]), "r"(a[1]), "r"(a[2]), "r"(a[3]), "r"(b0), "r"(b1));
}
__device__ __forceinline__ void mma_tf32(float d[4], const uint32_t a[4],
                                         uint32_t b0, uint32_t b1) {
    asm volatile("mma.sync.aligned.m16n8k8.row.col.f32.tf32.tf32.f32 "
        "{%0,%1,%2,%3}, {%4,%5,%6,%7}, {%8,%9}, {%0,%1,%2,%3};"
        : "+f"(d[0]), "+f"(d[1]), "+f"(d[2]), "+f"(d[3])
        : "r"(a[0]), "r"(a[1]), "r"(a[2]), "r"(a[3]), "r"(b0), "r"(b1));
}

// ---------------------------------------------------------------------------
// K0: prepack k1 weights (bf16 hi/lo images) + k2 W tf32 swizzled image.
// ---------------------------------------------------------------------------
__device__ __forceinline__ float catw(const float* Wr, const float* Wa, int k, int g) {
    if (g < 128) return Wr[k*128 + g];
    if (g < 256) return Wr[(64+k)*128 + (g-128)];
    if (g < 384) return Wa[k*128 + (g-256)];
    return Wa[(64+k)*128 + (g-384)];
}

__global__ void k0_kernel(const float* __restrict__ W_enc,
                          const float* __restrict__ W_self0,
                          const float* __restrict__ W_self1,
                          const float* __restrict__ W_rel0,
                          const float* __restrict__ W_att0,
                          const float* __restrict__ W_rel1,
                          const float* __restrict__ W_att1)
{
    int e = blockIdx.x * 256 + threadIdx.x;
    if (e < 22528) {
        int tile = e >> 11;
        int idx = e & 2047;
        int n = idx & 63, k0 = (idx >> 6) * 2;
        float v0, v1;
        if (tile == 0)      { v0 = W_enc[k0*64+n];   v1 = W_enc[(k0+1)*64+n]; }
        else if (tile == 1) { v0 = W_self0[k0*64+n]; v1 = W_self0[(k0+1)*64+n]; }
        else if (tile == 2) { v0 = W_self1[k0*64+n]; v1 = W_self1[(k0+1)*64+n]; }
        else {
            int g = (tile - 3) * 64 + n;
            v0 = catw(W_rel0, W_att0, k0, g);
            v1 = catw(W_rel0, W_att0, k0 + 1, g);
        }
        uint32_t hb, lb;
        split2(v0, v1, hb, lb);
        uint32_t off16 = (uint32_t)(tile*4096 + n*64 + (((k0>>3)*8) ^ ((n&7)*8)) + (k0&7));
        *(uint32_t*)((char*)g_WpkH + off16*2) = hb;
        *(uint32_t*)((char*)g_WpkL + off16*2) = lb;
    } else if (e < 38912) {
        int i2 = e - 22528;
        int hf = i2 >> 13;
        int i = i2 & 8191;
        int n = i & 63, k = i >> 6;
        float w = hf ? W_att1[k*64 + n] : W_rel1[k*64 + n];
        // exact k2 smem image: byte off = n*512 + ((k*4) ^ ((n&7)*16))
        uint32_t w32off = (uint32_t)(n*128 + ((((uint32_t)k*4) ^ (((uint32_t)n&7)*16)) >> 2));
        g_WtImg[hf*8192 + w32off] = f2tf32(w);
    }
}

// ---------------------------------------------------------------------------
// K1v2: R10 verbatim (monolithic grid).
// ---------------------------------------------------------------------------
#define K1_XHI 0
#define K1_XLO 16384
#define K1_EHI 32768
#define K1_ELO 49152
#define K1_WSH 65536
#define K1_WSL 90112
#define K1_WC  114688
#define K1_S01 147456
#define SMEM1_BYTES 148480

__device__ __forceinline__ void gemm_k64(uint32_t AH, uint32_t AL,
                                         uint32_t BH, uint32_t BL,
                                         int wm, int wn, int lane, float d[2][2][4])
{
    const int nloc = wn*16 + (lane & 7) + ((lane >> 4) << 3);
    const int nsw  = (lane & 7) * 16;
    const int bkc0 = (lane >> 3) & 1;
    const int rloc0 = wm*32 + (lane & 15);
    const int rsw  = (lane & 7) * 16;
    const int akc0 = lane >> 4;
#pragma unroll
    for (int ks = 0; ks < 4; ks++) {
        uint32_t bh[4], bl[4];
        {
            uint32_t boff = (uint32_t)(nloc*128 + (((ks*2 + bkc0)*16) ^ nsw));
            ldsm4(bh, BH + boff);
            ldsm4(bl, BL + boff);
        }
#pragma unroll
        for (int mt = 0; mt < 2; mt++) {
            uint32_t aoff = (uint32_t)((rloc0 + mt*16)*128 + (((ks*2 + akc0)*16) ^ rsw));
            uint32_t ah[4], al[4];
            ldsm4(ah, AH + aoff);
            ldsm4(al, AL + aoff);
            mma16816(d[mt][0], ah, bh[0], bh[1]);
            mma16816(d[mt][1], ah, bh[2], bh[3]);
            mma16816(d[mt][0], al, bh[0], bh[1]);
            mma16816(d[mt][1], al, bh[2], bh[3]);
            mma16816(d[mt][0], ah, bl[0], bl[1]);
            mma16816(d[mt][1], ah, bl[2], bl[3]);
        }
    }
}
#define K1_ZERO(d) { _Pragma("unroll") for (int _m=0;_m<2;_m++) _Pragma("unroll") for (int _n=0;_n<2;_n++) _Pragma("unroll") for (int _q=0;_q<4;_q++) (d)[_m][_n][_q]=0.f; }

__global__ __launch_bounds__(512, 1)
void k1_kernel(const float* __restrict__ s,
               const float* __restrict__ b_enc,
               const float* __restrict__ b_self0,
               const float* __restrict__ b_self1)
{
    extern __shared__ char smc[];
    const uint32_t smb = smem_u32(smc);
    const int tid = threadIdx.x, lane = tid & 31, wid = tid >> 5;
    const int wm = wid & 3, wn = wid >> 2;
    const int row0 = blockIdx.x * 128;
    float* s01 = (float*)(smc + K1_S01);

    {
        const uint4* srcH = (const uint4*)g_WpkH;
        const uint4* srcL = (const uint4*)g_WpkL;
#pragma unroll
        for (int q = 0; q < 3; q++) {
            ((uint4*)(smc + K1_WSH))[tid + q*512] = srcH[tid + q*512];
            ((uint4*)(smc + K1_WSL))[tid + q*512] = srcL[tid + q*512];
        }
    }
    uint4 pH = ((const uint4*)g_WpkH)[1536 + tid];
    uint4 pL = ((const uint4*)g_WpkL)[1536 + tid];

#pragma unroll
    for (int it = 0; it < 4; it++) {
        int idx = tid + it*512;
        int r = idx >> 4, kq = idx & 15, k0 = kq*4;
        float4 v = *(const float4*)(s + (size_t)(row0 + r)*64 + k0);
        if (kq == 0) { s01[r*2] = v.x; s01[r*2+1] = v.y; }
        uint32_t h0, l0, h1, l1;
        split2(v.x, v.y, h0, l0);
        split2(v.z, v.w, h1, l1);
        uint32_t off = (uint32_t)(r*128 + (((k0>>3)*16) ^ ((r&7)*16)) + (k0&7)*2);
        *(uint2*)(smc + K1_XHI + off) = make_uint2(h0, h1);
        *(uint2*)(smc + K1_XLO + off) = make_uint2(l0, l1);
    }

    const int c0b = wn*16 + (lane & 3)*2;
    float be[4], bs0[4], bs1[4];
    be[0]  = b_enc[c0b];    be[1]  = b_enc[c0b+1];
    be[2]  = b_enc[c0b+8];  be[3]  = b_enc[c0b+9];
    bs0[0] = b_self0[c0b];   bs0[1] = b_self0[c0b+1];
    bs0[2] = b_self0[c0b+8]; bs0[3] = b_self0[c0b+9];
    bs1[0] = b_self1[c0b];   bs1[1] = b_self1[c0b+1];
    bs1[2] = b_self1[c0b+8]; bs1[3] = b_self1[c0b+9];
    __syncthreads();

    float d[2][2][4];

    K1_ZERO(d);
    gemm_k64(smb + K1_XHI, smb + K1_XLO, smb + K1_WSH, smb + K1_WSL, wm, wn, lane, d);
#pragma unroll
    for (int mt = 0; mt < 2; mt++)
#pragma unroll
    for (int nt = 0; nt < 2; nt++)
#pragma unroll
    for (int h = 0; h < 2; h++) {
        int r = wm*32 + mt*16 + (lane >> 2) + h*8;
        int c0 = wn*16 + nt*8 + (lane & 3)*2;
        float v0 = d[mt][nt][h*2]     + be[nt*2];
        float v1 = d[mt][nt][h*2 + 1] + be[nt*2 + 1];
        if (c0 == 0) { v0 = s01[r*2]; v1 = s01[r*2+1]; }
        uint32_t hb, lb;
        split2(v0, v1, hb, lb);
        uint32_t off = (uint32_t)(r*128 + (((c0>>3)*16) ^ ((r&7)*16)) + (c0&7)*2);
        *(uint32_t*)(smc + K1_EHI + off) = hb;
        *(uint32_t*)(smc + K1_ELO + off) = lb;
    }
    __syncthreads();

    K1_ZERO(d);
    gemm_k64(smb + K1_EHI, smb + K1_ELO, smb + K1_WSH + 8192, smb + K1_WSL + 8192,
             wm, wn, lane, d);
    float hf[2][2][4];
#pragma unroll
    for (int mt = 0; mt < 2; mt++)
#pragma unroll
    for (int nt = 0; nt < 2; nt++)
#pragma unroll
    for (int h = 0; h < 2; h++) {
        int r = wm*32 + mt*16 + (lane >> 2) + h*8;
        int c0 = wn*16 + nt*8 + (lane & 3)*2;
        float v0 = eluf(d[mt][nt][h*2]     + bs0[nt*2]);
        float v1 = eluf(d[mt][nt][h*2 + 1] + bs0[nt*2 + 1]);
        hf[mt][nt][h*2] = v0; hf[mt][nt][h*2+1] = v1;
        uint32_t hb, lb;
        split2(v0, v1, hb, lb);
        uint32_t off = (uint32_t)(r*128 + (((c0>>3)*16) ^ ((r&7)*16)) + (c0&7)*2);
        *(uint32_t*)(smc + K1_XHI + off) = hb;
        *(uint32_t*)(smc + K1_XLO + off) = lb;
    }
    __syncthreads();

    *(uint4*)(smc + K1_WC + tid*16) = pH;
    *(uint4*)(smc + K1_WC + 8192 + tid*16) = pL;

    K1_ZERO(d);
    gemm_k64(smb + K1_XHI, smb + K1_XLO, smb + K1_WSH + 16384, smb + K1_WSL + 16384,
             wm, wn, lane, d);
#pragma unroll
    for (int mt = 0; mt < 2; mt++)
#pragma unroll
    for (int nt = 0; nt < 2; nt++)
#pragma unroll
    for (int h = 0; h < 2; h++) {
        int r = wm*32 + mt*16 + (lane >> 2) + h*8;
        int c0 = wn*16 + nt*8 + (lane & 3)*2;
        float2 o;
        o.x = d[mt][nt][h*2]     + bs1[nt*2]     + hf[mt][nt][h*2];
        o.y = d[mt][nt][h*2 + 1] + bs1[nt*2 + 1] + hf[mt][nt][h*2 + 1];
        *(float2*)&g_SD[(size_t)(row0 + r)*64 + c0] = o;
    }
    __syncthreads();

    for (int ch = 0; ch < 8; ch++) {
        if (ch < 7) {
            pH = ((const uint4*)g_WpkH)[1536 + (ch+1)*512 + tid];
            pL = ((const uint4*)g_WpkL)[1536 + (ch+1)*512 + tid];
        }
        K1_ZERO(d);
        const uint32_t wcb = smb + K1_WC + (uint32_t)(ch & 1)*16384;
        gemm_k64(smb + K1_EHI, smb + K1_ELO, wcb, wcb + 8192, wm, wn, lane, d);
#pragma unroll
        for (int mt = 0; mt < 2; mt++)
#pragma unroll
        for (int nt = 0; nt < 2; nt++)
#pragma unroll
        for (int h = 0; h < 2; h++) {
            int r = wm*32 + mt*16 + (lane >> 2) + h*8;
            int c0 = wn*16 + nt*8 + (lane & 3)*2;
            float2 o;
            o.x = d[mt][nt][h*2];
            o.y = d[mt][nt][h*2 + 1];
            *(float2*)&g_AB[(size_t)(row0 + r)*512 + ch*64 + c0] = o;
        }
        if (ch < 7) {
            const uint32_t dstoff = K1_WC + (uint32_t)((ch+1) & 1)*16384;
            *(uint4*)(smc + dstoff + tid*16) = pH;
            *(uint4*)(smc + dstoff + 8192 + tid*16) = pL;
            __syncthreads();
        }
    }
}

// ===========================================================================
// K2v4b: R10 verbatim (best-known-good) with W staging replaced by a linear
// coalesced copy of the prepacked tf32 swizzled image.
// ===========================================================================
#define SM2_XR   0
#define SM2_XA   65536
#define SM2_WR   131072
#define SM2_WA   163840
#define SM2_ABS  196608
#define SM2_WD   229376
#define SMEM2_BYTES 230400

__global__ __launch_bounds__(512, 1)
void k2_kernel(const float* __restrict__ s,
               const float* __restrict__ W_rel0, const float* __restrict__ b_rel0,
               const float* __restrict__ W_rel1, const float* __restrict__ b_rel1,
               const float* __restrict__ W_rel2, const float* __restrict__ b_rel2,
               const float* __restrict__ W_att0, const float* __restrict__ b_att0,
               const float* __restrict__ W_att1, const float* __restrict__ b_att1,
               const float* __restrict__ W_att2, const float* __restrict__ b_att2,
               float* __restrict__ out)
{
    extern __shared__ char smc[];
    const int tid  = threadIdx.x;
    const int wid  = tid >> 5;
    const int lane = tid & 31;
    const uint32_t smb = smem_u32(smc);

    const int half = wid >> 3;
    const int wg = wid & 7;
    const int wm = wg & 1;
    const int wn = wg >> 1;
    const int t2 = tid & 255;

    float* psmbuf = (float*)(smc + SM2_WD);
    float* b2r_s  = (float*)(smc + SM2_WD + 256);
    float* zv     = (float*)(smc + SM2_WD + 512);
    float* ABsf   = (float*)(smc + SM2_ABS);

    // ---- stage W tiles: linear coalesced copy of prepacked image ----
    {
        const uint4* src = (const uint4*)g_WtImg;
#pragma unroll
        for (int q = 0; q < 4; q++) {
            ((uint4*)(smc + SM2_WR))[tid + q*512] = src[tid + q*512];          // rel (8192 u32)
            ((uint4*)(smc + SM2_WA))[tid + q*512] = src[2048 + tid + q*512];   // att
        }
    }
    if (tid < 64) b2r_s[tid] = b_rel2[tid];
    const float b2a = b_att2[0];

    const int c0 = wn*16 + (lane & 3)*2;
    float b1c[4], w2c[4];
    if (half) {
        b1c[0] = b_att1[c0];   b1c[1] = b_att1[c0+1];
        b1c[2] = b_att1[c0+8]; b1c[3] = b_att1[c0+9];
        w2c[0] = W_att2[c0];   w2c[1] = W_att2[c0+1];
        w2c[2] = W_att2[c0+8]; w2c[3] = W_att2[c0+9];
    } else {
        b1c[0] = b_rel1[c0];   b1c[1] = b_rel1[c0+1];
        b1c[2] = b_rel1[c0+8]; b1c[3] = b_rel1[c0+9];
        w2c[0] = w2c[1] = w2c[2] = w2c[3] = 0.f;
    }
    float4 wd4, bv4;
    if (half) {
        wd4 = *(const float4*)&W_att0[128*128 + lane*4];
        bv4 = *(const float4*)&b_att0[lane*4];
    } else {
        wd4 = *(const float4*)&W_rel0[128*128 + lane*4];
        bv4 = *(const float4*)&b_rel0[lane*4];
    }

    {
        const float4* src = (const float4*)(g_AB + (size_t)(blockIdx.x*8) * 4096);
#pragma unroll
        for (int q = 0; q < 4; q++) ((float4*)ABsf)[tid + q*512] = src[tid + q*512];
        if (tid < 32)
            psmbuf[tid] = s[((size_t)(blockIdx.x*8 + (tid>>4)) * 8 + ((tid>>1)&7)) * 64 + (tid & 1)];
    }
    __syncthreads();

    const uint32_t xbo = (uint32_t)(half ? SM2_XA : SM2_XR);
    const int r0l = wm*64 + ((lane >> 3) & 1)*8 + (lane & 7);
    const uint32_t abase = smb + xbo + (uint32_t)(r0l * 512);
    const uint32_t arsw  = (uint32_t)((r0l & 7) << 4);
    const uint32_t aklane = (uint32_t)(((lane >> 4) & 1) << 4);
    const uint32_t wboff = (uint32_t)(half ? SM2_WA : SM2_WR)
                         + (uint32_t)((wn*16 + (lane >> 2)) * 512);
    const uint32_t bnsw = (uint32_t)((lane >> 2) << 4);
    const uint32_t bklo = (uint32_t)((lane & 3) << 2);
    const uint32_t xoff = ((uint32_t)(lane << 4)) ^ ((uint32_t)((wid & 7) << 4));

    for (int db = 0; db < 4; db++) {
        const int b0 = blockIdx.x * 8 + db * 2;
        const int nb = (db + 1) & 3;
        const int b0n = blockIdx.x * 8 + nb * 2;
        const float* psm = psmbuf + (db & 1) * 32;

        float4 pf[4];
        {
            const float* src = g_AB + (size_t)b0n * 4096;
#pragma unroll
            for (int q = 0; q < 4; q++) {
                int item = t2 + q*256;
                int row = item >> 6, f4 = (item & 63) + half*64;
                pf[q] = *(const float4*)(src + row*512 + f4*4);
            }
        }
        float psm_pf = 0.f;
        if (tid < 32)
            psm_pf = s[((size_t)(b0n + (tid>>4)) * 8 + ((tid>>1)&7)) * 64 + (tid & 1)];
        float gsd[8];
        if (half && t2 < 128) {
            int bb = t2 >> 6, c = t2 & 63;
#pragma unroll
            for (int i = 0; i < 8; i++)
                gsd[i] = g_SD[(size_t)((b0 + bb)*8 + i) * 64 + c];
        }

#pragma unroll
        for (int it = 0; it < 16; it++) {
            const int p_s = it*8 + (wid & 7);
            const int bbi = p_s >> 6, p = p_s & 63, i = p >> 3, j = p & 7;
            const float dx = psm[bbi*16 + 2*i]     - psm[bbi*16 + 2*j];
            const float dy = psm[bbi*16 + 2*i + 1] - psm[bbi*16 + 2*j + 1];
            const float d = dx*dx + dy*dy;
            const float* base = ABsf + bbi*4096 + half*256;
            float4 A4 = *(const float4*)(base + i*512 + lane*4);
            float4 B4 = *(const float4*)(base + j*512 + 128 + lane*4);
            uint4 o;
            o.x = f2tf32(eluf(A4.x + B4.x + fmaf(d, wd4.x, bv4.x)));
            o.y = f2tf32(eluf(A4.y + B4.y + fmaf(d, wd4.y, bv4.y)));
            o.z = f2tf32(eluf(A4.z + B4.z + fmaf(d, wd4.z, bv4.z)));
            o.w = f2tf32(eluf(A4.w + B4.w + fmaf(d, wd4.w, bv4.w)));
            *(uint4*)(smc + xbo + (uint32_t)(p_s * 512) + xoff) = o;
        }
        if (!half) asm volatile("bar.sync 1, 256;" ::: "memory");
        else       asm volatile("bar.sync 2, 256;" ::: "memory");

        float d[4][2][4];
#pragma unroll
        for (int mt = 0; mt < 4; mt++)
#pragma unroll
            for (int nt = 0; nt < 2; nt++)
#pragma unroll
                for (int q = 0; q < 4; q++) d[mt][nt][q] = 0.f;

#pragma unroll
        for (int ks = 0; ks < 16; ks++) {
            const uint32_t kb = (uint32_t)(ks * 32);
            uint32_t b00 = *(const uint32_t*)(smc + wboff + ((kb + bklo) ^ bnsw));
            uint32_t b01 = *(const uint32_t*)(smc + wboff + ((kb + bklo + 16) ^ bnsw));
            uint32_t b10 = *(const uint32_t*)(smc + wboff + 4096 + ((kb + bklo) ^ bnsw));
            uint32_t b11 = *(const uint32_t*)(smc + wboff + 4096 + ((kb + bklo + 16) ^ bnsw));
#pragma unroll
            for (int mt = 0; mt < 4; mt++) {
                uint32_t a[4];
                ldsm4(a, abase + (uint32_t)(mt * 8192) + ((kb + aklane) ^ arsw));
                mma_tf32(d[mt][0], a, b00, b01);
                mma_tf32(d[mt][1], a, b10, b11);
            }
        }

        if (!half) {
#pragma unroll
            for (int q = 0; q < 4; q++) {
                int item = t2 + q*256;
                int row = item >> 6, f4 = item & 63;
                *(float4*)(ABsf + row*512 + f4*4) = pf[q];
            }
            if (tid < 32) psmbuf[((db+1)&1)*32 + tid] = psm_pf;

#pragma unroll
            for (int mt = 0; mt < 4; mt++)
#pragma unroll
                for (int nt = 0; nt < 2; nt++)
#pragma unroll
                    for (int q = 0; q < 4; q++)
                        d[mt][nt][q] = eluf(d[mt][nt][q] + b1c[nt*2 + (q & 1)]);

            asm volatile("bar.sync 4, 512;" ::: "memory");

            float at[4][2];
#pragma unroll
            for (int mt = 0; mt < 4; mt++) {
                at[mt][0] = ABsf[1280 + wm*64 + mt*16 + (lane >> 2)];
                at[mt][1] = ABsf[1280 + wm*64 + mt*16 + 8 + (lane >> 2)];
            }
            float z0 = 0.f, z1 = 0.f, z2 = 0.f, z3 = 0.f;
#pragma unroll
            for (int mt = 0; mt < 4; mt++) {
                z0 += d[mt][0][0]*at[mt][0] + d[mt][0][2]*at[mt][1];
                z1 += d[mt][0][1]*at[mt][0] + d[mt][0][3]*at[mt][1];
                z2 += d[mt][1][0]*at[mt][0] + d[mt][1][2]*at[mt][1];
                z3 += d[mt][1][1]*at[mt][0] + d[mt][1][3]*at[mt][1];
            }
#pragma unroll
            for (int m = 4; m <= 16; m <<= 1) {
                z0 += __shfl_xor_sync(0xffffffffu, z0, m);
                z1 += __shfl_xor_sync(0xffffffffu, z1, m);
                z2 += __shfl_xor_sync(0xffffffffu, z2, m);
                z3 += __shfl_xor_sync(0xffffffffu, z3, m);
            }
            if (lane < 4) {
                zv[wm*64 + c0]     = z0;
                zv[wm*64 + c0 + 1] = z1;
                zv[wm*64 + c0 + 8] = z2;
                zv[wm*64 + c0 + 9] = z3;
            }
            asm volatile("bar.arrive 5, 512;" ::: "memory");
        } else {
#pragma unroll
            for (int mt = 0; mt < 4; mt++) {
#pragma unroll
                for (int h = 0; h < 2; h++) {
                    float v0 = eluf(d[mt][0][h*2]     + b1c[0]);
                    float v1 = eluf(d[mt][0][h*2 + 1] + b1c[1]);
                    float v2 = eluf(d[mt][1][h*2]     + b1c[2]);
                    float v3 = eluf(d[mt][1][h*2 + 1] + b1c[3]);
                    float part = v0*w2c[0] + v1*w2c[1] + v2*w2c[2] + v3*w2c[3];
                    part += __shfl_xor_sync(0xffffffffu, part, 1);
                    part += __shfl_xor_sync(0xffffffffu, part, 2);
                    if ((lane & 3) == 0) {
                        int idx = wn*128 + wm*64 + mt*16 + h*8 + (lane >> 2);
                        ABsf[(idx >> 8)*512 + 256 + (idx & 255)] = part;
                    }
                }
            }
            asm volatile("bar.sync 3, 256;" ::: "memory");

            if (t2 < 128) {
                const int p = t2 & 63, i = p >> 3, j = p & 7;
                float a = ABsf[256 + t2] + ABsf[384 + t2]
                        + ABsf[768 + t2] + ABsf[896 + t2] + b2a;
                ABsf[1280 + t2] = (i == j) ? 0.f : 1.f / (1.f + __expf(-a));
            }
            asm volatile("bar.arrive 4, 512;" ::: "memory");
            asm volatile("bar.sync 5, 512;" ::: "memory");

            if (t2 < 128) {
                const int bb = t2 >> 6, c = t2 & 63;
                float a0 = 0.f;
#pragma unroll
                for (int p = 0; p < 64; p++) a0 += ABsf[1280 + bb*64 + p];
                float sd = gsd[0] + gsd[1] + gsd[2] + gsd[3]
                         + gsd[4] + gsd[5] + gsd[6] + gsd[7];
                float o = zv[t2] + a0 * b2r_s[c] + sd;
#pragma unroll
                for (int k = 0; k < 64; k++)
                    o = fmaf(zv[bb*64 + k], W_rel2[k*64 + c], o);
                out[(size_t)(b0 + bb) * 64 + c] = o;
            }
            asm volatile("bar.sync 3, 256;" ::: "memory");

#pragma unroll
            for (int q = 0; q < 4; q++) {
                int item = t2 + q*256;
                int row = item >> 6, f4 = 64 + (item & 63);
                *(float4*)(ABsf + row*512 + f4*4) = pf[q];
            }
        }
        __syncthreads();
    }
}

// ---------------------------------------------------------------------------
extern "C" void kernel_launch(void* const* d_in, const int* in_sizes, int n_in,
                              void* d_out, int out_size)
{
    const float* s       = (const float*)d_in[0];
    const float* W_enc   = (const float*)d_in[1];
    const float* b_enc   = (const float*)d_in[2];
    const float* W_self0 = (const float*)d_in[3];
    const float* b_self0 = (const float*)d_in[4];
    const float* W_self1 = (const float*)d_in[5];
    const float* b_self1 = (const float*)d_in[6];
    const float* W_rel0  = (const float*)d_in[7];
    const float* b_rel0  = (const float*)d_in[8];
    const float* W_rel1  = (const float*)d_in[9];
    const float* b_rel1  = (const float*)d_in[10];
    const float* W_rel2  = (const float*)d_in[11];
    const float* b_rel2  = (const float*)d_in[12];
    const float* W_att0  = (const float*)d_in[13];
    const float* b_att0  = (const float*)d_in[14];
    const float* W_att1  = (const float*)d_in[15];
    const float* b_att1  = (const float*)d_in[16];
    const float* W_att2  = (const float*)d_in[17];
    const float* b_att2  = (const float*)d_in[18];
    float* out = (float*)d_out;

    cudaFuncSetAttribute(k1_kernel, cudaFuncAttributeMaxDynamicSharedMemorySize, SMEM1_BYTES);
    cudaFuncSetAttribute(k2_kernel, cudaFuncAttributeMaxDynamicSharedMemorySize, SMEM2_BYTES);

    k0_kernel<<<152, 256>>>(W_enc, W_self0, W_self1, W_rel0, W_att0, W_rel1, W_att1);
    k1_kernel<<<ROWS/128, 512, SMEM1_BYTES>>>(s, b_enc, b_self0, b_self1);
    k2_kernel<<<BATCH/8, 512, SMEM2_BYTES>>>(s, W_rel0, b_rel0, W_rel1, b_rel1,
                                             W_rel2, b_rel2, W_att0, b_att0,
                                             W_att1, b_att1, W_att2, b_att2, out);
}